// round 1
// baseline (speedup 1.0000x reference)
#include <cuda_runtime.h>
#include <cstdint>

// Problem constants (fixed by the reference).
#define NN 10000      // nodes
#define FF 256        // node feature dim
#define HH 256        // hidden dim
#define CDIM 512      // 2*HH columns in fused AB

// ---------------- scratch (allocation-free) ----------------
__device__ float g_AB[NN * CDIM];   // AB[n][0:256] = x[n]·W1[:, :F]^T ; AB[n][256:512] = x[n]·W1[:, F:]^T
__device__ int   g_idx64;           // 1 if edge_index is int64, 0 if int32

// ---------------- dtype detector ----------------
// If the buffer is really int32 pairs, reading as int64 combines two indices:
// value = lo + hi*2^32 with hi a random index in [0,10000) -> >= 2^32 almost surely.
__global__ void detect_idx_kernel(const long long* __restrict__ ei) {
    int ok = 1;
    for (int i = 0; i < 64; i++) {
        long long v = ei[i];
        if (v < 0 || v >= (long long)NN) { ok = 0; break; }
    }
    g_idx64 = ok;
}

// ---------------- phase 1: AB = x @ Wc^T  (M=10000, Ncols=512, K=256) ----------------
// Wc[c][f] = (c < 256) ? W1[c][f] : W1[c-256][256+f], W1 row-major (256, 512).
#define BM 64
#define BN 64
#define BK 16

__global__ __launch_bounds__(256) void gemm_kernel(const float* __restrict__ x,
                                                   const float* __restrict__ W1,
                                                   float* __restrict__ AB) {
    __shared__ float sX[BK][BM];
    __shared__ float sW[BK][BN];

    const int bm = blockIdx.x * BM;
    const int bn = blockIdx.y * BN;          // 0..448, multiple of 64 -> one side per block
    const int side = bn >> 8;                // 0: first F cols of W1 row, 1: second F
    const float* Wbase = W1 + side * 256;    // element offset inside each 512-wide row
    const int jbase = bn - side * 256;       // weight row of first column in this tile

    const int tid = threadIdx.x;             // 256 threads
    const int tx = tid & 15;
    const int ty = tid >> 4;
    const int lr = tid >> 2;                 // 0..63   (tile row for loads)
    const int lc = (tid & 3) << 2;           // 0,4,8,12 (k offset, float4)

    float acc[4][4] = {};

    for (int k0 = 0; k0 < FF; k0 += BK) {
        // load X tile (64 x 16) -> sX[k][m], zero-pad rows beyond NN
        float4 xv = make_float4(0.f, 0.f, 0.f, 0.f);
        int grow = bm + lr;
        if (grow < NN) xv = *(const float4*)(x + (size_t)grow * FF + k0 + lc);
        sX[lc + 0][lr] = xv.x; sX[lc + 1][lr] = xv.y;
        sX[lc + 2][lr] = xv.z; sX[lc + 3][lr] = xv.w;

        // load W tile (64 cols x 16 k) -> sW[k][c]
        float4 wv = *(const float4*)(Wbase + (size_t)(jbase + lr) * (2 * FF) + k0 + lc);
        sW[lc + 0][lr] = wv.x; sW[lc + 1][lr] = wv.y;
        sW[lc + 2][lr] = wv.z; sW[lc + 3][lr] = wv.w;

        __syncthreads();

        #pragma unroll
        for (int k = 0; k < BK; k++) {
            float4 a = *(const float4*)&sX[k][ty * 4];
            float4 b = *(const float4*)&sW[k][tx * 4];
            acc[0][0] += a.x * b.x; acc[0][1] += a.x * b.y; acc[0][2] += a.x * b.z; acc[0][3] += a.x * b.w;
            acc[1][0] += a.y * b.x; acc[1][1] += a.y * b.y; acc[1][2] += a.y * b.z; acc[1][3] += a.y * b.w;
            acc[2][0] += a.z * b.x; acc[2][1] += a.z * b.y; acc[2][2] += a.z * b.z; acc[2][3] += a.z * b.w;
            acc[3][0] += a.w * b.x; acc[3][1] += a.w * b.y; acc[3][2] += a.w * b.z; acc[3][3] += a.w * b.w;
        }
        __syncthreads();
    }

    #pragma unroll
    for (int i = 0; i < 4; i++) {
        int row = bm + ty * 4 + i;
        if (row < NN) {
            *(float4*)(AB + (size_t)row * CDIM + bn + tx * 4) =
                make_float4(acc[i][0], acc[i][1], acc[i][2], acc[i][3]);
        }
    }
}

// ---------------- phase 2: per-edge fused relu-dot-sigmoid (1 warp / edge) ----------------
__global__ __launch_bounds__(256) void edge_kernel(const long long* __restrict__ ei,
                                                   const float* __restrict__ b1,
                                                   const float* __restrict__ W2,
                                                   const float* __restrict__ b2,
                                                   float* __restrict__ out,
                                                   int E) {
    __shared__ float4 sB1[HH / 4];
    __shared__ float4 sW2[HH / 4];
    const int t = threadIdx.x;
    if (t < HH / 4) {
        sB1[t] = ((const float4*)b1)[t];
        sW2[t] = ((const float4*)W2)[t];
    }
    __syncthreads();

    const int e    = (int)((blockIdx.x * (unsigned)blockDim.x + t) >> 5);
    const int lane = t & 31;
    if (e >= E) return;

    long long r, c;
    if (g_idx64) {
        r = ei[e];
        c = ei[(size_t)E + e];
    } else {
        const int* ei32 = (const int*)ei;
        r = ei32[e];
        c = ei32[(size_t)E + e];
    }

    const float4* Arow = ((const float4*)g_AB) + (size_t)r * (CDIM / 4);        // A half
    const float4* Brow = ((const float4*)g_AB) + (size_t)c * (CDIM / 4) + 64;   // B half (+256 floats)

    float acc = 0.f;
    #pragma unroll
    for (int k = 0; k < 2; k++) {
        int idx = lane + 32 * k;                 // float4 index 0..63 -> j 0..255
        float4 a  = Arow[idx];
        float4 b  = Brow[idx];
        float4 bb = sB1[idx];
        float4 w  = sW2[idx];
        float hx = fmaxf(a.x + b.x + bb.x, 0.f);
        float hy = fmaxf(a.y + b.y + bb.y, 0.f);
        float hz = fmaxf(a.z + b.z + bb.z, 0.f);
        float hw = fmaxf(a.w + b.w + bb.w, 0.f);
        acc = fmaf(hx, w.x, acc);
        acc = fmaf(hy, w.y, acc);
        acc = fmaf(hz, w.z, acc);
        acc = fmaf(hw, w.w, acc);
    }

    // warp reduction
    #pragma unroll
    for (int o = 16; o > 0; o >>= 1) acc += __shfl_xor_sync(0xFFFFFFFFu, acc, o);

    if (lane == 0) {
        float z = acc + b2[0];                   // TEMPERATURE = 1
        out[e] = 1.f / (1.f + __expf(-z));
    }
}

// ---------------- launch ----------------
extern "C" void kernel_launch(void* const* d_in, const int* in_sizes, int n_in,
                              void* d_out, int out_size) {
    const float*     x  = (const float*)d_in[0];
    const long long* ei = (const long long*)d_in[1];
    const float*     W1 = (const float*)d_in[2];
    const float*     b1 = (const float*)d_in[3];
    const float*     W2 = (const float*)d_in[4];
    const float*     b2 = (const float*)d_in[5];
    float*           out = (float*)d_out;
    const int E = out_size;                      // 320000

    float* AB = nullptr;
    cudaGetSymbolAddress((void**)&AB, g_AB);

    detect_idx_kernel<<<1, 1>>>(ei);

    dim3 ggrid((NN + BM - 1) / BM, CDIM / BN);   // (157, 8)
    gemm_kernel<<<ggrid, 256>>>(x, W1, AB);

    int warps_per_block = 8;
    int blocks = (E + warps_per_block - 1) / warps_per_block;
    edge_kernel<<<blocks, warps_per_block * 32>>>(ei, b1, W2, b2, out, E);
}

// round 3
// speedup vs baseline: 1.4347x; 1.4347x over previous
#include <cuda_runtime.h>
#include <cuda_bf16.h>
#include <cuda_fp16.h>
#include <cstdint>

// ---------------- problem constants ----------------
#define NN   10000
#define FF   256
#define HH   256
#define CDIM 512                 // 2*HH fused output columns
#define KP   768                 // 3*FF concatenated K (hi|hi|lo vs hi|lo|hi)
#define BM   128
#define BN   64
#define BK   32
#define KITERS (KP / BK)         // 24
#define MTILES ((NN + BM - 1) / BM)  // 79
#define ASTRIDE 40               // smem row stride in bf16 (80B: 16B-aligned, conflict-free)

// ---------------- scratch (allocation-free) ----------------
__device__ __half        g_AB [(size_t)NN * CDIM];    // fp16 A|B rows (b1 folded into A half)
__device__ __nv_bfloat16 g_xcat[(size_t)NN * KP];     // [x_hi | x_hi | x_lo]
__device__ __nv_bfloat16 g_wcat[(size_t)CDIM * KP];   // [w_hi | w_lo | w_hi] (combined W rows)
__device__ int           g_idx64;

// ---------------- cp.async helpers (sm_80+ portable) ----------------
__device__ __forceinline__ uint32_t smem_u32(const void* p) {
    uint32_t a;
    asm("{ .reg .u64 t; cvta.to.shared.u64 t, %1; cvt.u32.u64 %0, t; }" : "=r"(a) : "l"(p));
    return a;
}
__device__ __forceinline__ void cp_async16(uint32_t dst, const void* src, int src_sz) {
    asm volatile("cp.async.cg.shared.global [%0], [%1], 16, %2;"
                 :: "r"(dst), "l"(src), "r"(src_sz) : "memory");
}
__device__ __forceinline__ void cp_commit() { asm volatile("cp.async.commit_group;" ::: "memory"); }
template <int N>
__device__ __forceinline__ void cp_wait() { asm volatile("cp.async.wait_group %0;" :: "n"(N) : "memory"); }

// ---------------- prep: build xcat / wcat + dtype detect ----------------
__global__ void prep_kernel(const float* __restrict__ x, const float* __restrict__ W1,
                            const long long* __restrict__ ei) {
    long long i = (long long)blockIdx.x * blockDim.x + threadIdx.x;
    if (i == 0) {
        int ok = 1;
        for (int t = 0; t < 64; t++) {
            long long v = ei[t];
            if (v < 0 || v >= (long long)NN) { ok = 0; break; }
        }
        g_idx64 = ok;
    }
    const long long XN = (long long)NN * KP;
    const long long TOT = XN + (long long)CDIM * KP;
    if (i < XN) {
        int n = (int)(i / KP), kp = (int)(i % KP);
        int k = kp & (FF - 1);
        float v = x[(size_t)n * FF + k];
        __nv_bfloat16 hi = __float2bfloat16(v);
        g_xcat[i] = (kp < 2 * FF) ? hi : __float2bfloat16(v - __bfloat162float(hi));
    } else if (i < TOT) {
        long long j = i - XN;
        int c = (int)(j / KP), kp = (int)(j % KP);
        int k = kp & (FF - 1);
        float v = (c < HH) ? W1[(size_t)c * CDIM + k] : W1[(size_t)(c - HH) * CDIM + FF + k];
        __nv_bfloat16 hi = __float2bfloat16(v);
        g_wcat[j] = (kp < FF || kp >= 2 * FF) ? hi : __float2bfloat16(v - __bfloat162float(hi));
    }
}

// ---------------- phase 1: bf16 mma.sync GEMM -> g_AB (fp16, b1 folded) ----------------
__global__ __launch_bounds__(256) void gemm_kernel(const float* __restrict__ b1) {
    __shared__ __align__(16) __nv_bfloat16 sA[2][BM * ASTRIDE];
    __shared__ __align__(16) __nv_bfloat16 sB[2][BN * ASTRIDE];
    __shared__ float sbias[BN];

    const int tid = threadIdx.x, lane = tid & 31, wid = tid >> 5;
    const int wm = wid & 3, wn = wid >> 2;            // 4x2 warp grid, 32x32 each
    const int g = lane >> 2, tc = lane & 3;
    const int bm = blockIdx.x * BM;
    const int bn = blockIdx.y * BN;
    const int side = bn >> 8;                         // 0 -> A half (bias), 1 -> B half

    if (tid < BN) sbias[tid] = (side == 0) ? b1[bn + tid] : 0.f;

    // async-load addressing (per thread, fixed across iters)
    // A: 512 16B-chunks (128 rows x 4 segs) -> 2 per thread; B: 256 chunks -> 1 per thread
    const int ar0 = tid >> 2, aseg0 = (tid & 3);            // chunk tid
    const int ar1 = (tid + 256) >> 2, aseg1 = (tid & 3);    // chunk tid+256
    const int brow = tid >> 2, bseg = tid & 3;
    const int arow0_ok = (bm + ar0) < NN ? 16 : 0;
    const int arow1_ok = (bm + ar1) < NN ? 16 : 0;
    const size_t agsrc0 = (size_t)(bm + ar0) * KP + aseg0 * 8;
    const size_t agsrc1 = (size_t)((bm + ar1) < NN ? (bm + ar1) : 0) * KP + aseg1 * 8;
    const size_t bgsrc  = (size_t)(bn + brow) * KP + bseg * 8;

    const uint32_t sA0 = smem_u32(&sA[0][0]), sA1 = smem_u32(&sA[1][0]);
    const uint32_t sB0 = smem_u32(&sB[0][0]), sB1 = smem_u32(&sB[1][0]);
    const uint32_t adst0 = (uint32_t)(ar0 * ASTRIDE + aseg0 * 8) * 2;
    const uint32_t adst1 = (uint32_t)(ar1 * ASTRIDE + aseg1 * 8) * 2;
    const uint32_t bdst  = (uint32_t)(brow * ASTRIDE + bseg * 8) * 2;

    float acc[2][4][4];
    #pragma unroll
    for (int mi = 0; mi < 2; mi++)
        #pragma unroll
        for (int ni = 0; ni < 4; ni++)
            #pragma unroll
            for (int q = 0; q < 4; q++) acc[mi][ni][q] = 0.f;

    // prefetch k0
    {
        cp_async16(sA0 + adst0, g_xcat + agsrc0, arow0_ok);
        cp_async16(sA0 + adst1, g_xcat + agsrc1, arow1_ok);
        cp_async16(sB0 + bdst,  g_wcat + bgsrc, 16);
        cp_commit();
    }

    for (int it = 0; it < KITERS; it++) {
        const int cur = it & 1;
        if (it + 1 < KITERS) {
            const int k0 = (it + 1) * BK;
            const uint32_t a_s = cur ? sA0 : sA1;   // next buffer
            const uint32_t b_s = cur ? sB0 : sB1;
            cp_async16(a_s + adst0, g_xcat + agsrc0 + k0, arow0_ok);
            cp_async16(a_s + adst1, g_xcat + agsrc1 + k0, arow1_ok);
            cp_async16(b_s + bdst,  g_wcat + bgsrc + k0, 16);
            cp_commit();
            cp_wait<1>();
        } else {
            cp_wait<0>();
        }
        __syncthreads();

        const __nv_bfloat16* A = sA[cur];
        const __nv_bfloat16* B = sB[cur];

        #pragma unroll
        for (int ks = 0; ks < BK; ks += 16) {
            uint32_t af[2][4], bf[4][2];
            #pragma unroll
            for (int mi = 0; mi < 2; mi++) {
                const __nv_bfloat16* ap = A + (wm * 32 + mi * 16 + g) * ASTRIDE + ks + tc * 2;
                af[mi][0] = *(const uint32_t*)(ap);
                af[mi][1] = *(const uint32_t*)(ap + 8 * ASTRIDE);
                af[mi][2] = *(const uint32_t*)(ap + 8);
                af[mi][3] = *(const uint32_t*)(ap + 8 * ASTRIDE + 8);
            }
            #pragma unroll
            for (int ni = 0; ni < 4; ni++) {
                const __nv_bfloat16* bp = B + (wn * 32 + ni * 8 + g) * ASTRIDE + ks + tc * 2;
                bf[ni][0] = *(const uint32_t*)(bp);
                bf[ni][1] = *(const uint32_t*)(bp + 8);
            }
            #pragma unroll
            for (int mi = 0; mi < 2; mi++)
                #pragma unroll
                for (int ni = 0; ni < 4; ni++) {
                    float* c = acc[mi][ni];
                    asm volatile(
                        "mma.sync.aligned.m16n8k16.row.col.f32.bf16.bf16.f32 "
                        "{%0,%1,%2,%3}, {%4,%5,%6,%7}, {%8,%9}, {%0,%1,%2,%3};"
                        : "+f"(c[0]), "+f"(c[1]), "+f"(c[2]), "+f"(c[3])
                        : "r"(af[mi][0]), "r"(af[mi][1]), "r"(af[mi][2]), "r"(af[mi][3]),
                          "r"(bf[ni][0]), "r"(bf[ni][1]));
                }
        }
        __syncthreads();
    }

    // epilogue: fp16 store with bias fold
    #pragma unroll
    for (int mi = 0; mi < 2; mi++) {
        const int row0 = bm + wm * 32 + mi * 16 + g;
        const int row1 = row0 + 8;
        #pragma unroll
        for (int ni = 0; ni < 4; ni++) {
            const int col = wn * 32 + ni * 8 + tc * 2;    // local col in [0,64)
            const float bx = sbias[col], by = sbias[col + 1];
            __half2 h0 = __floats2half2_rn(acc[mi][ni][0] + bx, acc[mi][ni][1] + by);
            __half2 h1 = __floats2half2_rn(acc[mi][ni][2] + bx, acc[mi][ni][3] + by);
            if (row0 < NN) *(__half2*)(g_AB + (size_t)row0 * CDIM + bn + col) = h0;
            if (row1 < NN) *(__half2*)(g_AB + (size_t)row1 * CDIM + bn + col) = h1;
        }
    }
}

// ---------------- phase 2: per-edge fused relu-dot-sigmoid (1 warp / edge, fp16 AB) --------
__global__ __launch_bounds__(256) void edge_kernel(const long long* __restrict__ ei,
                                                   const float* __restrict__ W2,
                                                   const float* __restrict__ b2,
                                                   float* __restrict__ out, int E) {
    const int t = threadIdx.x;
    const int e = (int)((blockIdx.x * 256u + t) >> 5);
    const int lane = t & 31;
    if (e >= E) return;

    long long r, c;
    if (g_idx64) {
        r = ei[e];
        c = ei[(size_t)E + e];
    } else {
        const int* p = (const int*)ei;
        r = p[e];
        c = p[(size_t)E + e];
    }

    const uint4 av = *((const uint4*)(g_AB + (size_t)r * CDIM) + lane);        // A cols (b1 folded)
    const uint4 bv = *((const uint4*)(g_AB + (size_t)c * CDIM + HH) + lane);   // B cols
    const float4 w0 = ((const float4*)W2)[lane * 2];
    const float4 w1 = ((const float4*)W2)[lane * 2 + 1];

    const __half2 z2 = __float2half2_rn(0.f);
    __half2 a0 = *(const __half2*)&av.x, a1 = *(const __half2*)&av.y,
            a2 = *(const __half2*)&av.z, a3 = *(const __half2*)&av.w;
    __half2 b0 = *(const __half2*)&bv.x, b1h = *(const __half2*)&bv.y,
            b2h = *(const __half2*)&bv.z, b3 = *(const __half2*)&bv.w;

    __half2 h0 = __hmax2(__hadd2(a0, b0), z2);
    __half2 h1 = __hmax2(__hadd2(a1, b1h), z2);
    __half2 h2 = __hmax2(__hadd2(a2, b2h), z2);
    __half2 h3 = __hmax2(__hadd2(a3, b3), z2);

    float2 f0 = __half22float2(h0), f1 = __half22float2(h1);
    float2 f2 = __half22float2(h2), f3 = __half22float2(h3);

    float acc = 0.f;
    acc = fmaf(f0.x, w0.x, acc); acc = fmaf(f0.y, w0.y, acc);
    acc = fmaf(f1.x, w0.z, acc); acc = fmaf(f1.y, w0.w, acc);
    acc = fmaf(f2.x, w1.x, acc); acc = fmaf(f2.y, w1.y, acc);
    acc = fmaf(f3.x, w1.z, acc); acc = fmaf(f3.y, w1.w, acc);

    #pragma unroll
    for (int o = 16; o > 0; o >>= 1) acc += __shfl_xor_sync(0xFFFFFFFFu, acc, o);

    if (lane == 0) {
        float z = acc + b2[0];                   // TEMPERATURE = 1
        out[e] = 1.f / (1.f + __expf(-z));
    }
}

// ---------------- launch ----------------
extern "C" void kernel_launch(void* const* d_in, const int* in_sizes, int n_in,
                              void* d_out, int out_size) {
    const float*     x   = (const float*)d_in[0];
    const long long* ei  = (const long long*)d_in[1];
    const float*     W1  = (const float*)d_in[2];
    const float*     b1  = (const float*)d_in[3];
    const float*     W2  = (const float*)d_in[4];
    const float*     b2  = (const float*)d_in[5];
    float*           out = (float*)d_out;
    const int E = out_size;   // 320000

    long long tot = (long long)NN * KP + (long long)CDIM * KP;
    int pblocks = (int)((tot + 255) / 256);
    prep_kernel<<<pblocks, 256>>>(x, W1, ei);

    dim3 ggrid(MTILES, CDIM / BN);   // (79, 8)
    gemm_kernel<<<ggrid, 256>>>(b1);

    int eblocks = (E + 7) / 8;       // 8 warps/block, 1 warp/edge
    edge_kernel<<<eblocks, 256>>>(ei, W2, b2, out, E);
}

// round 4
// speedup vs baseline: 1.8953x; 1.3211x over previous
#include <cuda_runtime.h>
#include <cuda_fp16.h>
#include <cstdint>

// ---------------- problem constants ----------------
#define NN   10000
#define FF   256
#define HH   256
#define CDIM 512                 // 2*HH fused output columns
#define KP   512                 // GEMM K': [hi-pass | lo-pass]; A reuses x_hi via (k & 255)
#define BM   128
#define BN   64
#define BK   32
#define KITERS (KP / BK)         // 16
#define MTILES ((NN + BM - 1) / BM)  // 79
#define ASTRIDE 40               // smem row stride in halves (80B: 16B-aligned, conflict-free)

// ---------------- scratch (allocation-free) ----------------
__device__ __half g_AB [(size_t)NN * CDIM];    // fp16 A|B rows (b1 folded into A half)
__device__ __half g_xh [(size_t)NN * FF];      // x rounded to fp16
__device__ __half g_wcat[(size_t)CDIM * KP];   // per combined row c: [w_hi(256) | w_lo(256)]
__device__ int    g_idx64;

// ---------------- PTX helpers ----------------
__device__ __forceinline__ uint32_t smem_u32(const void* p) {
    uint32_t a;
    asm("{ .reg .u64 t; cvta.to.shared.u64 t, %1; cvt.u32.u64 %0, t; }" : "=r"(a) : "l"(p));
    return a;
}
__device__ __forceinline__ void cp_async16(uint32_t dst, const void* src, int src_sz) {
    asm volatile("cp.async.cg.shared.global [%0], [%1], 16, %2;"
                 :: "r"(dst), "l"(src), "r"(src_sz) : "memory");
}
__device__ __forceinline__ void cp_commit() { asm volatile("cp.async.commit_group;" ::: "memory"); }
template <int N>
__device__ __forceinline__ void cp_wait() { asm volatile("cp.async.wait_group %0;" :: "n"(N) : "memory"); }

__device__ __forceinline__ void ldm_x4(uint32_t& r0, uint32_t& r1, uint32_t& r2, uint32_t& r3,
                                       uint32_t addr) {
    asm volatile("ldmatrix.sync.aligned.m8n8.x4.shared.b16 {%0,%1,%2,%3}, [%4];"
                 : "=r"(r0), "=r"(r1), "=r"(r2), "=r"(r3) : "r"(addr));
}

// ---------------- prep: fp16 conversions + dtype detect ----------------
// tasks: [0, XQ)           : x float4 -> 4 halves            (XQ = NN*FF/4)
//        [XQ, XQ+WQ)       : W float4 -> hi quad + lo quad   (WQ = CDIM*FF/4)
#define XQ (NN * FF / 4)
#define WQ (CDIM * FF / 4)
__global__ void prep_kernel(const float* __restrict__ x, const float* __restrict__ W1,
                            const long long* __restrict__ ei) {
    const int i = blockIdx.x * blockDim.x + threadIdx.x;
    if (i == 0) {
        int ok = 1;
        for (int t = 0; t < 64; t++) {
            long long v = ei[t];
            if (v < 0 || v >= (long long)NN) { ok = 0; break; }
        }
        g_idx64 = ok;
    }
    if (i < XQ) {
        const int n = i >> 6, k4 = (i & 63) << 2;
        float4 v = *(const float4*)(x + ((size_t)n << 8) + k4);
        __half2 h0 = __floats2half2_rn(v.x, v.y);
        __half2 h1 = __floats2half2_rn(v.z, v.w);
        *(uint2*)(g_xh + ((size_t)n << 8) + k4) =
            make_uint2(*(uint32_t*)&h0, *(uint32_t*)&h1);
    } else if (i < XQ + WQ) {
        const int j = i - XQ;
        const int c = j >> 6, k4 = (j & 63) << 2;
        const float* src = (c < HH) ? (W1 + ((size_t)c << 9) + k4)
                                    : (W1 + ((size_t)(c - HH) << 9) + FF + k4);
        float4 v = *(const float4*)src;
        __half2 h0 = __floats2half2_rn(v.x, v.y);
        __half2 h1 = __floats2half2_rn(v.z, v.w);
        float2 f0 = __half22float2(h0), f1 = __half22float2(h1);
        __half2 l0 = __floats2half2_rn(v.x - f0.x, v.y - f0.y);
        __half2 l1 = __floats2half2_rn(v.z - f1.x, v.w - f1.y);
        __half* rowp = g_wcat + ((size_t)c << 9);
        *(uint2*)(rowp + k4)      = make_uint2(*(uint32_t*)&h0, *(uint32_t*)&h1);
        *(uint2*)(rowp + FF + k4) = make_uint2(*(uint32_t*)&l0, *(uint32_t*)&l1);
    }
}

// ---------------- phase 1: fp16x2 mma.sync GEMM -> g_AB (fp16, b1 folded) ----------------
__global__ __launch_bounds__(256) void gemm_kernel(const float* __restrict__ b1) {
    __shared__ __align__(16) __half sA[2][BM * ASTRIDE];
    __shared__ __align__(16) __half sB[2][BN * ASTRIDE];
    __shared__ float sbias[BN];

    const int tid = threadIdx.x, lane = tid & 31, wid = tid >> 5;
    const int wm = wid & 3, wn = wid >> 2;            // 4x2 warp grid, 32x32 each
    const int g = lane >> 2, tc = lane & 3;
    const int bm = blockIdx.x * BM;
    const int bn = blockIdx.y * BN;
    const int side = bn >> 8;                         // 0 -> A half (bias), 1 -> B half

    if (tid < BN) sbias[tid] = (side == 0) ? b1[bn + tid] : 0.f;

    // cp.async addressing: A 512 16B-chunks (2/thread), B 256 chunks (1/thread)
    const int ar0 = tid >> 2,           aseg = tid & 3;
    const int ar1 = (tid + 256) >> 2;
    const int brow = tid >> 2,          bseg = tid & 3;
    const int arow0_ok = (bm + ar0) < NN ? 16 : 0;
    const int arow1_ok = (bm + ar1) < NN ? 16 : 0;
    const __half* agp0 = g_xh + ((size_t)(bm + ar0) << 8) + aseg * 8;
    const __half* agp1 = g_xh + ((size_t)((bm + ar1) < NN ? (bm + ar1) : 0) << 8) + aseg * 8;
    const __half* bgp  = g_wcat + ((size_t)(bn + brow) << 9) + bseg * 8;

    const uint32_t sA0 = smem_u32(&sA[0][0]), sA1 = smem_u32(&sA[1][0]);
    const uint32_t sB0 = smem_u32(&sB[0][0]), sB1 = smem_u32(&sB[1][0]);
    const uint32_t adst0 = (uint32_t)(ar0 * ASTRIDE + aseg * 8) * 2;
    const uint32_t adst1 = (uint32_t)(ar1 * ASTRIDE + aseg * 8) * 2;
    const uint32_t bdst  = (uint32_t)(brow * ASTRIDE + bseg * 8) * 2;

    // ldmatrix per-lane offsets (bytes)
    const uint32_t a_loff = (uint32_t)(((wm * 32 + (lane & 15)) * ASTRIDE + (lane >> 4) * 8) * 2);
    const int b_rl = lane & 7, b_q = lane >> 3;
    const uint32_t b_loff = (uint32_t)(((wn * 32 + (b_q >> 1) * 8 + b_rl) * ASTRIDE + (b_q & 1) * 8) * 2);

    float acc[2][4][4];
    #pragma unroll
    for (int mi = 0; mi < 2; mi++)
        #pragma unroll
        for (int ni = 0; ni < 4; ni++)
            #pragma unroll
            for (int q = 0; q < 4; q++) acc[mi][ni][q] = 0.f;

    // prefetch k0
    cp_async16(sA0 + adst0, agp0, arow0_ok);
    cp_async16(sA0 + adst1, agp1, arow1_ok);
    cp_async16(sB0 + bdst,  bgp,  16);
    cp_commit();

    for (int it = 0; it < KITERS; it++) {
        const int cur = it & 1;
        if (it + 1 < KITERS) {
            const int k0n = (it + 1) * BK;
            const int ak  = k0n & (FF - 1);            // A reuses x_hi both passes
            const uint32_t a_s = cur ? sA0 : sA1;
            const uint32_t b_s = cur ? sB0 : sB1;
            cp_async16(a_s + adst0, agp0 + ak, arow0_ok);
            cp_async16(a_s + adst1, agp1 + ak, arow1_ok);
            cp_async16(b_s + bdst,  bgp + k0n, 16);
            cp_commit();
            cp_wait<1>();
        } else {
            cp_wait<0>();
        }
        __syncthreads();

        const uint32_t As = (cur ? sA1 : sA0) + a_loff;
        const uint32_t Bs = (cur ? sB1 : sB0) + b_loff;

        #pragma unroll
        for (int ks = 0; ks < BK; ks += 16) {
            uint32_t af[2][4], bf[4][2];
            #pragma unroll
            for (int mi = 0; mi < 2; mi++)
                ldm_x4(af[mi][0], af[mi][1], af[mi][2], af[mi][3],
                       As + (uint32_t)((mi * 16 * ASTRIDE + ks) * 2));
            #pragma unroll
            for (int p = 0; p < 2; p++)
                ldm_x4(bf[2 * p][0], bf[2 * p][1], bf[2 * p + 1][0], bf[2 * p + 1][1],
                       Bs + (uint32_t)((p * 16 * ASTRIDE + ks) * 2));
            #pragma unroll
            for (int mi = 0; mi < 2; mi++)
                #pragma unroll
                for (int ni = 0; ni < 4; ni++) {
                    float* c = acc[mi][ni];
                    asm volatile(
                        "mma.sync.aligned.m16n8k16.row.col.f32.f16.f16.f32 "
                        "{%0,%1,%2,%3}, {%4,%5,%6,%7}, {%8,%9}, {%0,%1,%2,%3};"
                        : "+f"(c[0]), "+f"(c[1]), "+f"(c[2]), "+f"(c[3])
                        : "r"(af[mi][0]), "r"(af[mi][1]), "r"(af[mi][2]), "r"(af[mi][3]),
                          "r"(bf[ni][0]), "r"(bf[ni][1]));
                }
        }
        __syncthreads();
    }

    // epilogue: fp16 store with bias fold
    #pragma unroll
    for (int mi = 0; mi < 2; mi++) {
        const int row0 = bm + wm * 32 + mi * 16 + g;
        const int row1 = row0 + 8;
        #pragma unroll
        for (int ni = 0; ni < 4; ni++) {
            const int col = wn * 32 + ni * 8 + tc * 2;
            const float bx = sbias[col], by = sbias[col + 1];
            __half2 h0 = __floats2half2_rn(acc[mi][ni][0] + bx, acc[mi][ni][1] + by);
            __half2 h1 = __floats2half2_rn(acc[mi][ni][2] + bx, acc[mi][ni][3] + by);
            if (row0 < NN) *(__half2*)(g_AB + (size_t)row0 * CDIM + bn + col) = h0;
            if (row1 < NN) *(__half2*)(g_AB + (size_t)row1 * CDIM + bn + col) = h1;
        }
    }
}

// ---------------- phase 2: per-edge fused relu-dot-sigmoid (1 warp / edge, fp16 AB) --------
__global__ __launch_bounds__(256) void edge_kernel(const long long* __restrict__ ei,
                                                   const float* __restrict__ W2,
                                                   const float* __restrict__ b2,
                                                   float* __restrict__ out, int E) {
    const int t = threadIdx.x;
    const int e = (int)((blockIdx.x * 256u + t) >> 5);
    const int lane = t & 31;
    if (e >= E) return;

    long long r, c;
    if (g_idx64) {
        r = ei[e];
        c = ei[(size_t)E + e];
    } else {
        const int* p = (const int*)ei;
        r = p[e];
        c = p[(size_t)E + e];
    }

    const uint4 av = *((const uint4*)(g_AB + (size_t)r * CDIM) + lane);        // A cols (b1 folded)
    const uint4 bv = *((const uint4*)(g_AB + (size_t)c * CDIM + HH) + lane);   // B cols
    const float4 w0 = ((const float4*)W2)[lane * 2];
    const float4 w1 = ((const float4*)W2)[lane * 2 + 1];

    const __half2 z2 = __float2half2_rn(0.f);
    __half2 a0 = *(const __half2*)&av.x, a1 = *(const __half2*)&av.y,
            a2 = *(const __half2*)&av.z, a3 = *(const __half2*)&av.w;
    __half2 b0 = *(const __half2*)&bv.x, b1h = *(const __half2*)&bv.y,
            b2h = *(const __half2*)&bv.z, b3 = *(const __half2*)&bv.w;

    __half2 h0 = __hmax2(__hadd2(a0, b0), z2);
    __half2 h1 = __hmax2(__hadd2(a1, b1h), z2);
    __half2 h2 = __hmax2(__hadd2(a2, b2h), z2);
    __half2 h3 = __hmax2(__hadd2(a3, b3), z2);

    float2 f0 = __half22float2(h0), f1 = __half22float2(h1);
    float2 f2 = __half22float2(h2), f3 = __half22float2(h3);

    float acc = 0.f;
    acc = fmaf(f0.x, w0.x, acc); acc = fmaf(f0.y, w0.y, acc);
    acc = fmaf(f1.x, w0.z, acc); acc = fmaf(f1.y, w0.w, acc);
    acc = fmaf(f2.x, w1.x, acc); acc = fmaf(f2.y, w1.y, acc);
    acc = fmaf(f3.x, w1.z, acc); acc = fmaf(f3.y, w1.w, acc);

    #pragma unroll
    for (int o = 16; o > 0; o >>= 1) acc += __shfl_xor_sync(0xFFFFFFFFu, acc, o);

    if (lane == 0) {
        float z = acc + b2[0];                   // TEMPERATURE = 1
        out[e] = 1.f / (1.f + __expf(-z));
    }
}

// ---------------- launch ----------------
extern "C" void kernel_launch(void* const* d_in, const int* in_sizes, int n_in,
                              void* d_out, int out_size) {
    const float*     x   = (const float*)d_in[0];
    const long long* ei  = (const long long*)d_in[1];
    const float*     W1  = (const float*)d_in[2];
    const float*     b1  = (const float*)d_in[3];
    const float*     W2  = (const float*)d_in[4];
    const float*     b2  = (const float*)d_in[5];
    float*           out = (float*)d_out;
    const int E = out_size;   // 320000

    const int ptasks = XQ + WQ;                      // 672768
    prep_kernel<<<(ptasks + 255) / 256, 256>>>(x, W1, ei);

    dim3 ggrid(MTILES, CDIM / BN);                   // (79, 8)
    gemm_kernel<<<ggrid, 256>>>(b1);

    int eblocks = (E + 7) / 8;                       // 1 warp/edge
    edge_kernel<<<eblocks, 256>>>(ei, W2, b2, out, E);
}

// round 5
// speedup vs baseline: 1.9910x; 1.0505x over previous
#include <cuda_runtime.h>
#include <cuda_fp16.h>
#include <cstdint>

// ---------------- problem constants ----------------
#define NN   10000
#define FF   256
#define HH   256
#define CDIM 512                 // 2*HH fused output columns
#define KP   512                 // GEMM K': [hi-pass | lo-pass]; A reuses x_hi via (k & 255)
#define BM   128
#define BN   64
#define BK   32
#define KITERS (KP / BK)         // 16
#define MTILES ((NN + BM - 1) / BM)  // 79
#define ASTRIDE 40               // smem row stride in halves (80B: 16B-aligned, conflict-free)
#define NSTAGE 4
#define ABYTES (BM * ASTRIDE * 2)   // 10240 per stage
#define BBYTES (BN * ASTRIDE * 2)   // 5120 per stage
#define SMEM_TOTAL (NSTAGE * (ABYTES + BBYTES) + BN * 4)   // 61696

// ---------------- scratch (allocation-free) ----------------
__device__ __half g_AB [(size_t)NN * CDIM];    // fp16 A|B rows (b1 folded into A half)
__device__ __half g_xh [(size_t)NN * FF];      // x rounded to fp16
__device__ __half g_wcat[(size_t)CDIM * KP];   // per combined row c: [w_hi(256) | w_lo(256)]
__device__ int    g_idx64;

// ---------------- PTX helpers ----------------
__device__ __forceinline__ uint32_t smem_u32(const void* p) {
    uint32_t a;
    asm("{ .reg .u64 t; cvta.to.shared.u64 t, %1; cvt.u32.u64 %0, t; }" : "=r"(a) : "l"(p));
    return a;
}
__device__ __forceinline__ void cp_async16(uint32_t dst, const void* src, int src_sz) {
    asm volatile("cp.async.cg.shared.global [%0], [%1], 16, %2;"
                 :: "r"(dst), "l"(src), "r"(src_sz) : "memory");
}
__device__ __forceinline__ void cp_commit() { asm volatile("cp.async.commit_group;" ::: "memory"); }
template <int N>
__device__ __forceinline__ void cp_wait() { asm volatile("cp.async.wait_group %0;" :: "n"(N) : "memory"); }

__device__ __forceinline__ void ldm_x4(uint32_t& r0, uint32_t& r1, uint32_t& r2, uint32_t& r3,
                                       uint32_t addr) {
    asm volatile("ldmatrix.sync.aligned.m8n8.x4.shared.b16 {%0,%1,%2,%3}, [%4];"
                 : "=r"(r0), "=r"(r1), "=r"(r2), "=r"(r3) : "r"(addr));
}

// ---------------- prep: fp16 conversions + dtype detect (8 floats / thread) ------------
#define XQ8 (NN * FF / 8)        // 320000
#define WQ8 (CDIM * FF / 8)      // 16384
__global__ void prep_kernel(const float* __restrict__ x, const float* __restrict__ W1,
                            const long long* __restrict__ ei) {
    const int i = blockIdx.x * blockDim.x + threadIdx.x;
    if (i == 0) {
        int ok = 1;
        for (int t = 0; t < 64; t++) {
            long long v = ei[t];
            if (v < 0 || v >= (long long)NN) { ok = 0; break; }
        }
        g_idx64 = ok;
    }
    if (i < XQ8) {
        const int n = i >> 5, k8 = (i & 31) << 3;
        const float* sp = x + ((size_t)n << 8) + k8;
        float4 v0 = *(const float4*)sp;
        float4 v1 = *(const float4*)(sp + 4);
        __half2 h0 = __floats2half2_rn(v0.x, v0.y), h1 = __floats2half2_rn(v0.z, v0.w);
        __half2 h2 = __floats2half2_rn(v1.x, v1.y), h3 = __floats2half2_rn(v1.z, v1.w);
        *(uint4*)(g_xh + ((size_t)n << 8) + k8) =
            make_uint4(*(uint32_t*)&h0, *(uint32_t*)&h1, *(uint32_t*)&h2, *(uint32_t*)&h3);
    } else if (i < XQ8 + WQ8) {
        const int j = i - XQ8;
        const int c = j >> 5, k8 = (j & 31) << 3;
        const float* src = (c < HH) ? (W1 + ((size_t)c << 9) + k8)
                                    : (W1 + ((size_t)(c - HH) << 9) + FF + k8);
        float4 v0 = *(const float4*)src;
        float4 v1 = *(const float4*)(src + 4);
        __half2 h0 = __floats2half2_rn(v0.x, v0.y), h1 = __floats2half2_rn(v0.z, v0.w);
        __half2 h2 = __floats2half2_rn(v1.x, v1.y), h3 = __floats2half2_rn(v1.z, v1.w);
        float2 f0 = __half22float2(h0), f1 = __half22float2(h1);
        float2 f2 = __half22float2(h2), f3 = __half22float2(h3);
        __half2 l0 = __floats2half2_rn(v0.x - f0.x, v0.y - f0.y);
        __half2 l1 = __floats2half2_rn(v0.z - f1.x, v0.w - f1.y);
        __half2 l2 = __floats2half2_rn(v1.x - f2.x, v1.y - f2.y);
        __half2 l3 = __floats2half2_rn(v1.z - f3.x, v1.w - f3.y);
        __half* rowp = g_wcat + ((size_t)c << 9);
        *(uint4*)(rowp + k8) =
            make_uint4(*(uint32_t*)&h0, *(uint32_t*)&h1, *(uint32_t*)&h2, *(uint32_t*)&h3);
        *(uint4*)(rowp + FF + k8) =
            make_uint4(*(uint32_t*)&l0, *(uint32_t*)&l1, *(uint32_t*)&l2, *(uint32_t*)&l3);
    }
}

// ---------------- phase 1: fp16x2 mma.sync GEMM, 4-stage pipeline -> g_AB ----------------
__global__ __launch_bounds__(256) void gemm_kernel(const float* __restrict__ b1) {
    extern __shared__ __align__(16) char smem[];
    __half* sbias_area = (__half*)(smem + NSTAGE * (ABYTES + BBYTES));
    float*  sbias = (float*)sbias_area;

    const int tid = threadIdx.x, lane = tid & 31, wid = tid >> 5;
    const int wm = wid & 3, wn = wid >> 2;            // 4x2 warp grid, 32x32 each
    const int g = lane >> 2, tc = lane & 3;
    const int bm = blockIdx.x * BM;
    const int bn = blockIdx.y * BN;
    const int side = bn >> 8;                         // 0 -> A half (bias), 1 -> B half

    if (tid < BN) sbias[tid] = (side == 0) ? b1[bn + tid] : 0.f;

    // cp.async addressing: A 512 16B-chunks (2/thread), B 256 chunks (1/thread)
    const int ar0 = tid >> 2,           aseg = tid & 3;
    const int ar1 = (tid + 256) >> 2;
    const int brow = tid >> 2,          bseg = tid & 3;
    const int arow0_ok = (bm + ar0) < NN ? 16 : 0;
    const int arow1_ok = (bm + ar1) < NN ? 16 : 0;
    const __half* agp0 = g_xh + ((size_t)((bm + ar0) < NN ? (bm + ar0) : 0) << 8) + aseg * 8;
    const __half* agp1 = g_xh + ((size_t)((bm + ar1) < NN ? (bm + ar1) : 0) << 8) + aseg * 8;
    const __half* bgp  = g_wcat + ((size_t)(bn + brow) << 9) + bseg * 8;

    const uint32_t smem_base = smem_u32(smem);
    uint32_t aS[NSTAGE], bS[NSTAGE];
    #pragma unroll
    for (int s = 0; s < NSTAGE; s++) {
        aS[s] = smem_base + s * ABYTES;
        bS[s] = smem_base + NSTAGE * ABYTES + s * BBYTES;
    }
    const uint32_t adst0 = (uint32_t)(ar0 * ASTRIDE + aseg * 8) * 2;
    const uint32_t adst1 = (uint32_t)(ar1 * ASTRIDE + aseg * 8) * 2;
    const uint32_t bdst  = (uint32_t)(brow * ASTRIDE + bseg * 8) * 2;

    // ldmatrix per-lane offsets (bytes)
    const uint32_t a_loff = (uint32_t)(((wm * 32 + (lane & 15)) * ASTRIDE + (lane >> 4) * 8) * 2);
    const int b_rl = lane & 7, b_q = lane >> 3;
    const uint32_t b_loff = (uint32_t)(((wn * 32 + (b_q >> 1) * 8 + b_rl) * ASTRIDE + (b_q & 1) * 8) * 2);

    float acc[2][4][4];
    #pragma unroll
    for (int mi = 0; mi < 2; mi++)
        #pragma unroll
        for (int ni = 0; ni < 4; ni++)
            #pragma unroll
            for (int q = 0; q < 4; q++) acc[mi][ni][q] = 0.f;

    // prologue: fill stages 0..NSTAGE-2
    #pragma unroll
    for (int it = 0; it < NSTAGE - 1; it++) {
        const int k0 = it * BK, ak = k0 & (FF - 1);
        cp_async16(aS[it] + adst0, agp0 + ak, arow0_ok);
        cp_async16(aS[it] + adst1, agp1 + ak, arow1_ok);
        cp_async16(bS[it] + bdst,  bgp + k0, 16);
        cp_commit();
    }

    for (int it = 0; it < KITERS; it++) {
        cp_wait<NSTAGE - 2>();     // stage it arrived (<=2 groups pending)
        __syncthreads();           // data visible + prior compute done with stage (it+3)&3

        {                          // issue stage it+3 (or empty commit to keep counts aligned)
            const int nf = it + NSTAGE - 1;
            if (nf < KITERS) {
                const int s = nf & (NSTAGE - 1);
                const int k0 = nf * BK, ak = k0 & (FF - 1);
                cp_async16(aS[s] + adst0, agp0 + ak, arow0_ok);
                cp_async16(aS[s] + adst1, agp1 + ak, arow1_ok);
                cp_async16(bS[s] + bdst,  bgp + k0, 16);
            }
            cp_commit();
        }

        const int s = it & (NSTAGE - 1);
        const uint32_t As = aS[s] + a_loff;
        const uint32_t Bs = bS[s] + b_loff;

        #pragma unroll
        for (int ks = 0; ks < BK; ks += 16) {
            uint32_t af[2][4], bf[4][2];
            #pragma unroll
            for (int mi = 0; mi < 2; mi++)
                ldm_x4(af[mi][0], af[mi][1], af[mi][2], af[mi][3],
                       As + (uint32_t)((mi * 16 * ASTRIDE + ks) * 2));
            #pragma unroll
            for (int p = 0; p < 2; p++)
                ldm_x4(bf[2 * p][0], bf[2 * p][1], bf[2 * p + 1][0], bf[2 * p + 1][1],
                       Bs + (uint32_t)((p * 16 * ASTRIDE + ks) * 2));
            #pragma unroll
            for (int mi = 0; mi < 2; mi++)
                #pragma unroll
                for (int ni = 0; ni < 4; ni++) {
                    float* c = acc[mi][ni];
                    asm volatile(
                        "mma.sync.aligned.m16n8k16.row.col.f32.f16.f16.f32 "
                        "{%0,%1,%2,%3}, {%4,%5,%6,%7}, {%8,%9}, {%0,%1,%2,%3};"
                        : "+f"(c[0]), "+f"(c[1]), "+f"(c[2]), "+f"(c[3])
                        : "r"(af[mi][0]), "r"(af[mi][1]), "r"(af[mi][2]), "r"(af[mi][3]),
                          "r"(bf[ni][0]), "r"(bf[ni][1]));
                }
        }
    }

    // epilogue: fp16 store with bias fold
    #pragma unroll
    for (int mi = 0; mi < 2; mi++) {
        const int row0 = bm + wm * 32 + mi * 16 + g;
        const int row1 = row0 + 8;
        #pragma unroll
        for (int ni = 0; ni < 4; ni++) {
            const int col = wn * 32 + ni * 8 + tc * 2;
            const float bx = sbias[col], by = sbias[col + 1];
            __half2 h0 = __floats2half2_rn(acc[mi][ni][0] + bx, acc[mi][ni][1] + by);
            __half2 h1 = __floats2half2_rn(acc[mi][ni][2] + bx, acc[mi][ni][3] + by);
            if (row0 < NN) *(__half2*)(g_AB + (size_t)row0 * CDIM + bn + col) = h0;
            if (row1 < NN) *(__half2*)(g_AB + (size_t)row1 * CDIM + bn + col) = h1;
        }
    }
}

// ---------------- phase 2: per-edge fused relu-dot-sigmoid (1 warp / edge, fp16 AB) --------
__global__ __launch_bounds__(256) void edge_kernel(const long long* __restrict__ ei,
                                                   const float* __restrict__ W2,
                                                   const float* __restrict__ b2,
                                                   float* __restrict__ out, int E) {
    const int t = threadIdx.x;
    const int e = (int)((blockIdx.x * 256u + t) >> 5);
    const int lane = t & 31;
    if (e >= E) return;

    long long r, c;
    if (g_idx64) {
        r = ei[e];
        c = ei[(size_t)E + e];
    } else {
        const int* p = (const int*)ei;
        r = p[e];
        c = p[(size_t)E + e];
    }

    const uint4 av = *((const uint4*)(g_AB + (size_t)r * CDIM) + lane);        // A cols (b1 folded)
    const uint4 bv = *((const uint4*)(g_AB + (size_t)c * CDIM + HH) + lane);   // B cols
    const float4 w0 = ((const float4*)W2)[lane * 2];
    const float4 w1 = ((const float4*)W2)[lane * 2 + 1];

    const __half2 z2 = __float2half2_rn(0.f);
    __half2 a0 = *(const __half2*)&av.x, a1 = *(const __half2*)&av.y,
            a2 = *(const __half2*)&av.z, a3 = *(const __half2*)&av.w;
    __half2 b0 = *(const __half2*)&bv.x, b1h = *(const __half2*)&bv.y,
            b2h = *(const __half2*)&bv.z, b3 = *(const __half2*)&bv.w;

    __half2 h0 = __hmax2(__hadd2(a0, b0), z2);
    __half2 h1 = __hmax2(__hadd2(a1, b1h), z2);
    __half2 h2 = __hmax2(__hadd2(a2, b2h), z2);
    __half2 h3 = __hmax2(__hadd2(a3, b3), z2);

    float2 f0 = __half22float2(h0), f1 = __half22float2(h1);
    float2 f2 = __half22float2(h2), f3 = __half22float2(h3);

    float acc = 0.f;
    acc = fmaf(f0.x, w0.x, acc); acc = fmaf(f0.y, w0.y, acc);
    acc = fmaf(f1.x, w0.z, acc); acc = fmaf(f1.y, w0.w, acc);
    acc = fmaf(f2.x, w1.x, acc); acc = fmaf(f2.y, w1.y, acc);
    acc = fmaf(f3.x, w1.z, acc); acc = fmaf(f3.y, w1.w, acc);

    #pragma unroll
    for (int o = 16; o > 0; o >>= 1) acc += __shfl_xor_sync(0xFFFFFFFFu, acc, o);

    if (lane == 0) {
        float z = acc + b2[0];                   // TEMPERATURE = 1
        out[e] = 1.f / (1.f + __expf(-z));
    }
}

// ---------------- launch ----------------
extern "C" void kernel_launch(void* const* d_in, const int* in_sizes, int n_in,
                              void* d_out, int out_size) {
    const float*     x   = (const float*)d_in[0];
    const long long* ei  = (const long long*)d_in[1];
    const float*     W1  = (const float*)d_in[2];
    const float*     b1  = (const float*)d_in[3];
    const float*     W2  = (const float*)d_in[4];
    const float*     b2  = (const float*)d_in[5];
    float*           out = (float*)d_out;
    const int E = out_size;   // 320000

    const int ptasks = XQ8 + WQ8;                    // 336384
    prep_kernel<<<(ptasks + 255) / 256, 256>>>(x, W1, ei);

    static int smem_set = 0;
    cudaFuncSetAttribute(gemm_kernel, cudaFuncAttributeMaxDynamicSharedMemorySize, SMEM_TOTAL);
    (void)smem_set;

    dim3 ggrid(MTILES, CDIM / BN);                   // (79, 8)
    gemm_kernel<<<ggrid, 256, SMEM_TOTAL>>>(b1);

    int eblocks = (E + 7) / 8;                       // 1 warp/edge
    edge_kernel<<<eblocks, 256>>>(ei, W2, b2, out, E);
}